// round 16
// baseline (speedup 1.0000x reference)
#include <cuda_runtime.h>
#include <stdint.h>

// RGBMem: inverted-index single-sweep, cp.async.bulk pipelined (2 launches).
//   logits[b,k] = dot(memory[row(b,k)], x[b]) / T,  row(b,0)=y[b], else idx[b,k]
//   labels = zeros
//   new_memory = memory with rows y[b] := normalize(0.5*memory[y]+0.5*x[b])
// Output (float32): [logits (bsz*Kp1)] [labels gap] [memory (n_data*128)]
// R16: the 512MB copy moves via cp.async.bulk (async proxy) through 3 SMEM
// stages; compute (logits/EMA) reads SMEM. R13-R15 falsified occupancy/issue/
// MLP as binders -> suspect per-SM LDG/STG request path; bulk bypasses it.

#define T_INV (1.0f / 0.07f)
#define MAX_ROWS 524288
#define CAP 16
#define TILE_ROWS 64u
#define NSTAGE 3
#define STAGE_F4 (TILE_ROWS * 32u)          // float4 per stage
#define SMEM_MBAR_OFF 0
#define SMEM_XS_OFF 128
#define SMEM_STAGE_OFF (128 + 8192)
#define SMEM_TOTAL (128 + 8192 + NSTAGE * TILE_ROWS * 512)   // 106624 B

__device__ uint2 g_meta[MAX_ROWS];                   // .x=count, .y=upd flag
__device__ unsigned g_list[(size_t)MAX_ROWS * CAP];  // 32 MB scratch

__device__ __forceinline__ long long load_index(const void* p, unsigned i,
                                                int is64) {
    if (is64) return ((const long long*)p)[i];
    return (long long)((const int*)p)[i];
}

__device__ __forceinline__ int sniff_is64(const void* idx) {
    const unsigned* w = (const unsigned*)idx;
    int is64 = 1;
    #pragma unroll
    for (int i = 0; i < 16; i++)
        if (w[2 * i + 1] != 0u) { is64 = 0; break; }
    return is64;
}

// ---- async-proxy helpers -------------------------------------------------
__device__ __forceinline__ unsigned smem_u32(const void* p) {
    return (unsigned)__cvta_generic_to_shared(p);
}
__device__ __forceinline__ void mbar_init(unsigned mbar, unsigned count) {
    asm volatile("mbarrier.init.shared.b64 [%0], %1;"
                 :: "r"(mbar), "r"(count) : "memory");
}
__device__ __forceinline__ void mbar_expect_tx(unsigned mbar, unsigned bytes) {
    asm volatile("mbarrier.arrive.expect_tx.shared.b64 _, [%0], %1;"
                 :: "r"(mbar), "r"(bytes) : "memory");
}
__device__ __forceinline__ void mbar_wait_parity(unsigned mbar,
                                                 unsigned parity) {
    asm volatile(
        "{\n\t.reg .pred P;\n\t"
        "WAITLOOP_%=:\n\t"
        "mbarrier.try_wait.parity.acquire.cta.shared::cta.b64 P, [%0], %1, 0x989680;\n\t"
        "@P bra.uni WDONE_%=;\n\t"
        "bra.uni WAITLOOP_%=;\n\t"
        "WDONE_%=:\n\t}"
        :: "r"(mbar), "r"(parity) : "memory");
}
__device__ __forceinline__ void bulk_load(unsigned sdst, const void* gsrc,
                                          unsigned bytes, unsigned mbar) {
    asm volatile(
        "cp.async.bulk.shared::cluster.global.mbarrier::complete_tx::bytes "
        "[%0], [%1], %2, [%3];"
        :: "r"(sdst), "l"(gsrc), "r"(bytes), "r"(mbar) : "memory");
}
__device__ __forceinline__ void bulk_store(void* gdst, unsigned ssrc,
                                           unsigned bytes) {
    asm volatile("cp.async.bulk.global.shared::cta.bulk_group [%0], [%1], %2;"
                 :: "l"(gdst), "r"(ssrc), "r"(bytes) : "memory");
}
__device__ __forceinline__ void bulk_commit() {
    asm volatile("cp.async.bulk.commit_group;" ::: "memory");
}
__device__ __forceinline__ void bulk_wait_read1() {
    asm volatile("cp.async.bulk.wait_group.read 1;" ::: "memory");
}
__device__ __forceinline__ void bulk_wait0() {
    asm volatile("cp.async.bulk.wait_group 0;" ::: "memory");
}
__device__ __forceinline__ void fence_proxy_async_sc() {
    asm volatile("fence.proxy.async.shared::cta;" ::: "memory");
}

// ---------------------------------------------------------------------------
// Build: inverted lists (entry = (b<<24)|i), update flags, labels zeroing.
// ---------------------------------------------------------------------------
__global__ void build_kernel(const float* __restrict__ x,
                             const void* __restrict__ y,
                             const void* __restrict__ idx,
                             const float* __restrict__ memory,
                             float* __restrict__ logits,
                             float* __restrict__ out_labels, int label_elems,
                             int bsz, unsigned Kp1, long long n_data) {
    __shared__ int s_is64;
    if (threadIdx.x == 0) s_is64 = sniff_is64(idx);
    __syncthreads();
    int is64 = s_is64;

    if (blockIdx.x == 0) {
        if (threadIdx.x < (unsigned)bsz) {
            long long r = load_index(y, threadIdx.x, is64);
            r = r < 0 ? 0 : (r >= n_data ? n_data - 1 : r);
            atomicMax(&g_meta[r].y, threadIdx.x + 1u);   // last-write-wins
        }
        for (int t = threadIdx.x; t < label_elems; t += blockDim.x)
            out_labels[t] = 0.0f;
    }

    unsigned total = (unsigned)bsz * Kp1;
    unsigned i = blockIdx.x * blockDim.x + threadIdx.x;
    unsigned stride = gridDim.x * blockDim.x;
    for (; i < total; i += stride) {
        unsigned b = i / Kp1;
        unsigned k = i - b * Kp1;
        long long row = (k == 0) ? load_index(y, b, is64)
                                 : load_index(idx, i, is64);
        row = row < 0 ? 0 : (row >= n_data ? n_data - 1 : row);
        unsigned p = atomicAdd(&g_meta[row].x, 1u);
        if (p < CAP) {
            g_list[(size_t)row * CAP + p] = (b << 24) | i;
        } else {
            const float* mr = memory + row * 128;
            const float* xr = x + b * 128;
            float s = 0.0f;
            for (int d = 0; d < 128; d++) s += __ldg(mr + d) * __ldg(xr + d);
            logits[i] = s * T_INV;
        }
    }
}

// ---------------------------------------------------------------------------
// Bulk-pipelined sweep: per block, contiguous row chunk; 3 SMEM stages of 64
// rows; bulk loads in, compute logits/EMA from SMEM, bulk store out.
// ---------------------------------------------------------------------------
__global__ void __launch_bounds__(256) sweep_bulk_kernel(
    const float* __restrict__ x,
    const float* __restrict__ memory,
    float* __restrict__ out_mem,
    float* __restrict__ logits,
    unsigned n_data) {
    extern __shared__ unsigned char smem_raw[];
    float4* xs = (float4*)(smem_raw + SMEM_XS_OFF);
    float4* stages = (float4*)(smem_raw + SMEM_STAGE_OFF);
    unsigned mbar0 = smem_u32(smem_raw + SMEM_MBAR_OFF);

    int tid = threadIdx.x;
    for (int i = tid; i < 512; i += blockDim.x)
        xs[i] = ((const float4*)x)[i];
    if (tid == 0) {
        #pragma unroll
        for (int s = 0; s < NSTAGE; s++) mbar_init(mbar0 + s * 8, 1);
        fence_proxy_async_sc();
    }
    __syncthreads();

    unsigned chunk = (n_data + gridDim.x - 1) / gridDim.x;
    unsigned row0 = (unsigned)blockIdx.x * chunk;
    unsigned rows = (row0 < n_data) ? min(chunk, n_data - row0) : 0u;
    int T = (int)((rows + TILE_ROWS - 1) / TILE_ROWS);

    const float4* gsrc_base = (const float4*)memory;
    float4* gdst_base = (float4*)out_mem;
    unsigned stage_su32 = smem_u32(stages);

    // prologue: tiles 0,1 -> stages 0,1
    if (tid == 0) {
        for (int p = 0; p < (T < 2 ? T : 2); p++) {
            unsigned rt = min(TILE_ROWS, rows - (unsigned)p * TILE_ROWS);
            unsigned bytes = rt * 512u;
            mbar_expect_tx(mbar0 + p * 8, bytes);
            bulk_load(stage_su32 + (unsigned)p * (STAGE_F4 * 16u),
                      gsrc_base + ((size_t)row0 + (size_t)p * TILE_ROWS) * 32,
                      bytes, mbar0 + p * 8);
        }
    }

    int wid = tid >> 5, lane = tid & 31;

    for (int t = 0; t < T; t++) {
        int s = t % NSTAGE;
        unsigned parity = (unsigned)((t / NSTAGE) & 1);
        mbar_wait_parity(mbar0 + s * 8, parity);

        unsigned rt = min(TILE_ROWS, rows - (unsigned)t * TILE_ROWS);
        float4* stg = stages + (size_t)s * STAGE_F4;

        for (unsigned lr = (unsigned)wid; lr < rt; lr += 8u) {
            unsigned r = row0 + (unsigned)t * TILE_ROWS + lr;
            float4 m = stg[lr * 32u + lane];          // LDS, row resident
            uint2 meta = g_meta[r];                   // broadcast LDG
            unsigned c = meta.x > CAP ? CAP : meta.x;

            const uint4* lst4 = (const uint4*)(g_list + (size_t)r * CAP);
            for (unsigned base = 0; base < c; base += 4u) {
                uint4 L = lst4[base >> 2];
                #pragma unroll
                for (int j = 0; j < 4; j++) {
                    unsigned e = base + (unsigned)j;
                    if (e >= c) break;
                    unsigned ent = (j == 0) ? L.x : (j == 1) ? L.y
                                 : (j == 2) ? L.z : L.w;
                    unsigned b = (ent >> 24) & 15u;
                    unsigned i = ent & 0xFFFFFFu;
                    float4 xv = xs[b * 32u + lane];
                    float sd = m.x * xv.x + m.y * xv.y +
                               m.z * xv.z + m.w * xv.w;
                    #pragma unroll
                    for (int off = 16; off; off >>= 1)
                        sd += __shfl_xor_sync(0xffffffffu, sd, off);
                    if (lane == 0) __stcs(logits + i, sd * T_INV);
                }
            }

            if (meta.y) {   // EMA row: whole warp, uniform, full mask OK
                unsigned b = meta.y - 1u;
                float4 xv = xs[b * 32u + lane];
                float4 v;
                v.x = 0.5f * (m.x + xv.x); v.y = 0.5f * (m.y + xv.y);
                v.z = 0.5f * (m.z + xv.z); v.w = 0.5f * (m.w + xv.w);
                float ss = v.x * v.x + v.y * v.y + v.z * v.z + v.w * v.w;
                #pragma unroll
                for (int off = 16; off; off >>= 1)
                    ss += __shfl_xor_sync(0xffffffffu, ss, off);
                float inv = 1.0f / fmaxf(sqrtf(ss), 1e-12f);
                v.x *= inv; v.y *= inv; v.z *= inv; v.w *= inv;
                stg[lr * 32u + lane] = v;             // patch row in SMEM
            }
            if (lane == 0 && (meta.x | meta.y))
                g_meta[r] = make_uint2(0u, 0u);       // self-clean (dirty only)
        }
        __syncthreads();   // tile fully computed/patched before store

        if (tid == 0) {
            fence_proxy_async_sc();                   // generic STS -> async
            bulk_store(gdst_base + ((size_t)row0 + (size_t)t * TILE_ROWS) * 32,
                       stage_su32 + (unsigned)s * (STAGE_F4 * 16u),
                       rt * 512u);
            bulk_commit();
            bulk_wait_read1();                        // free oldest stage
            int tn = t + 2;
            if (tn < T) {
                unsigned rtn = min(TILE_ROWS, rows - (unsigned)tn * TILE_ROWS);
                unsigned bytes = rtn * 512u;
                int sn = tn % NSTAGE;
                mbar_expect_tx(mbar0 + sn * 8, bytes);
                bulk_load(stage_su32 + (unsigned)sn * (STAGE_F4 * 16u),
                          gsrc_base +
                              ((size_t)row0 + (size_t)tn * TILE_ROWS) * 32,
                          bytes, mbar0 + sn * 8);
            }
        }
    }
    if (tid == 0) bulk_wait0();                       // drain stores
}

// ---------------------------------------------------------------------------
// Fallback path (shape out of range): R2-proven kernels.
// ---------------------------------------------------------------------------
__global__ void copy_mem_kernel(const float4* __restrict__ src,
                                float4* __restrict__ dst, long long n4) {
    long long i = (long long)blockIdx.x * blockDim.x + threadIdx.x;
    long long stride = (long long)gridDim.x * blockDim.x;
    for (; i < n4; i += stride) dst[i] = src[i];
}

__global__ void logits_kernel(const float* __restrict__ x,
                              const void* __restrict__ y,
                              const void* __restrict__ idx,
                              const float* __restrict__ memory,
                              float* __restrict__ logits,
                              int bsz, unsigned Kp1, long long n_data) {
    __shared__ float4 xs[16 * 32];
    __shared__ int s_is64;
    int tid = threadIdx.x;
    if (tid == 0) s_is64 = sniff_is64(idx);
    int nx4 = bsz * 32;
    for (int i = tid; i < nx4; i += blockDim.x) xs[i] = ((const float4*)x)[i];
    __syncthreads();
    int is64 = s_is64;

    int lane = tid & 31;
    unsigned warp = (blockIdx.x * blockDim.x + tid) >> 5;
    unsigned nwarps = (gridDim.x * blockDim.x) >> 5;
    unsigned total = (unsigned)bsz * Kp1;

    for (unsigned i = warp; i < total; i += nwarps) {
        unsigned b = i / Kp1;
        unsigned k = i - b * Kp1;
        long long row = (k == 0) ? load_index(y, b, is64)
                                 : load_index(idx, i, is64);
        row = row < 0 ? 0 : (row >= n_data ? n_data - 1 : row);
        float4 mm = __ldg((const float4*)(memory + row * 128) + lane);
        float4 xv = xs[b * 32 + lane];
        float s = mm.x * xv.x + mm.y * xv.y + mm.z * xv.z + mm.w * xv.w;
        #pragma unroll
        for (int off = 16; off; off >>= 1)
            s += __shfl_xor_sync(0xffffffffu, s, off);
        if (lane == 0) logits[i] = s * T_INV;
    }
}

__global__ void update_kernel(const float* __restrict__ x,
                              const void* __restrict__ y,
                              const void* __restrict__ idx,
                              const float* __restrict__ memory,
                              float* __restrict__ out_mem,
                              float* __restrict__ out_labels,
                              int label_elems, long long n_data) {
    int b = blockIdx.x;
    int t = threadIdx.x;
    __shared__ int s_is64;
    if (t == 0) s_is64 = sniff_is64(idx);
    __syncthreads();
    long long row = load_index(y, (unsigned)b, s_is64);
    row = row < 0 ? 0 : (row >= n_data ? n_data - 1 : row);

    float v = memory[row * 128 + t] * 0.5f + x[b * 128 + t] * 0.5f;
    float s = v * v;
    #pragma unroll
    for (int off = 16; off; off >>= 1)
        s += __shfl_xor_sync(0xffffffffu, s, off);
    __shared__ float ws[4];
    if ((t & 31) == 0) ws[t >> 5] = s;
    __syncthreads();
    float tot = ws[0] + ws[1] + ws[2] + ws[3];
    float denom = fmaxf(sqrtf(tot), 1e-12f);
    out_mem[row * 128 + t] = v / denom;
    if (b == 0 && t < label_elems) out_labels[t] = 0.0f;
}

// ---------------------------------------------------------------------------
extern "C" void kernel_launch(void* const* d_in, const int* in_sizes, int n_in,
                              void* d_out, int out_size) {
    const float* x      = (const float*)d_in[0];   // [bsz, 128]
    const void*  y      = d_in[1];                 // [bsz]
    const void*  idx    = d_in[2];                 // [bsz, K+1]
    const float* memory = (const float*)d_in[3];   // [n_data, 128]

    int bsz = in_sizes[1];
    unsigned Kp1 = (unsigned)(in_sizes[2] / bsz);
    long long mem_elems = (long long)in_sizes[3];
    long long n_data = mem_elems / 128;
    long long logits_elems = (long long)bsz * Kp1;

    float* out = (float*)d_out;
    long long mem_off = (long long)out_size - mem_elems;
    if (mem_off < logits_elems) mem_off = logits_elems;
    float* out_mem = out + mem_off;
    float* out_labels = out + logits_elems;
    int label_elems = (int)(mem_off - logits_elems);

    int sms = 0;
    cudaDeviceGetAttribute(&sms, cudaDevAttrMultiProcessorCount, 0);
    if (sms <= 0) sms = 148;

    bool aligned16 = ((mem_off * 4) % 16 == 0) &&
                     (((uintptr_t)memory) % 16 == 0) &&
                     (((uintptr_t)out) % 16 == 0);

    if (n_data <= MAX_ROWS && bsz <= 16 && logits_elems < (1 << 24) &&
        aligned16) {
        unsigned total = (unsigned)logits_elems;
        build_kernel<<<(total + 255) / 256, 256>>>(x, y, idx, memory, out,
                                                   out_labels, label_elems,
                                                   bsz, Kp1, n_data);
        static bool attr_set = false;
        if (!attr_set) {
            cudaFuncSetAttribute(sweep_bulk_kernel,
                                 cudaFuncAttributeMaxDynamicSharedMemorySize,
                                 SMEM_TOTAL);
            attr_set = true;
        }
        sweep_bulk_kernel<<<sms * 2, 256, SMEM_TOTAL>>>(
            x, memory, out_mem, out, (unsigned)n_data);
    } else {
        copy_mem_kernel<<<2048, 256>>>((const float4*)memory,
                                       (float4*)out_mem, mem_elems / 4);
        logits_kernel<<<1184, 256>>>(x, y, idx, memory, out,
                                     bsz, Kp1, n_data);
        update_kernel<<<bsz, 128>>>(x, y, idx, memory, out_mem, out_labels,
                                    label_elems, n_data);
    }
}

// round 17
// speedup vs baseline: 2.8534x; 2.8534x over previous
#include <cuda_runtime.h>
#include <stdint.h>

// RGBMem: inverted-index single-sweep, ONE persistent fused kernel.
//   logits[b,k] = dot(memory[row(b,k)], x[b]) / T,  row(b,0)=y[b], else idx[b,k]
//   labels = zeros
//   new_memory = memory with rows y[b] := normalize(0.5*memory[y]+0.5*x[b])
// Output (float32): [logits (bsz*Kp1)] [labels gap] [memory (n_data*128)]
// R17: build + sweep fused with a software grid barrier (grid = one resident
// wave at 8 blocks/SM, so spinning is safe). Sweep body is the proven R14
// 2-rows-per-warp shape (~5.5 TB/s, at the measured mixed-R/W roofline).

#define T_INV (1.0f / 0.07f)
#define MAX_ROWS 524288
#define CAP 16

__device__ uint2 g_meta[MAX_ROWS];                   // .x=count, .y=upd flag
__device__ unsigned g_list[(size_t)MAX_ROWS * CAP];  // 32 MB scratch
__device__ unsigned g_bar;                           // monotonic ticket ctr

__device__ __forceinline__ long long load_index(const void* p, unsigned i,
                                                int is64) {
    if (is64) return ((const long long*)p)[i];
    return (long long)((const int*)p)[i];
}

__device__ __forceinline__ int sniff_is64(const void* idx) {
    const unsigned* w = (const unsigned*)idx;
    int is64 = 1;
    #pragma unroll
    for (int i = 0; i < 16; i++)
        if (w[2 * i + 1] != 0u) { is64 = 0; break; }
    return is64;
}

// ---------------------------------------------------------------------------
// Fused persistent kernel: Phase A builds inverted lists; software grid
// barrier; Phase B streams the table (copy/EMA + all dot products).
// Requires: grid == one fully-resident wave (gridDim = sms * 8 @ 32 regs).
// ---------------------------------------------------------------------------
__global__ void __launch_bounds__(256, 8) fused_kernel(
    const float* __restrict__ x,
    const void* __restrict__ y,
    const void* __restrict__ idx,
    const float4* __restrict__ mem4,
    float4* __restrict__ out_mem4,
    float* __restrict__ logits,
    float* __restrict__ out_labels, int label_elems,
    int bsz, unsigned Kp1, unsigned n_data) {
    __shared__ float4 xs[16 * 32];
    __shared__ int s_is64;
    int tid = threadIdx.x;
    if (tid == 0) s_is64 = sniff_is64(idx);
    for (int i = tid; i < 16 * 32; i += blockDim.x)
        xs[i] = ((const float4*)x)[i];
    __syncthreads();
    int is64 = s_is64;

    // ===== Phase A: build =====
    if (blockIdx.x == 0) {
        if (tid < bsz) {
            long long r = load_index(y, tid, is64);
            r = r < 0 ? 0 : (r >= (long long)n_data ? n_data - 1 : r);
            atomicMax(&g_meta[r].y, (unsigned)tid + 1u);  // last-write-wins
        }
        for (int t = tid; t < label_elems; t += blockDim.x)
            out_labels[t] = 0.0f;
    }
    {
        unsigned total = (unsigned)bsz * Kp1;
        unsigned i = blockIdx.x * blockDim.x + tid;
        unsigned stride = gridDim.x * blockDim.x;
        const float* memf = (const float*)mem4;
        for (; i < total; i += stride) {
            unsigned b = i / Kp1;
            unsigned k = i - b * Kp1;
            long long row = (k == 0) ? load_index(y, b, is64)
                                     : load_index(idx, i, is64);
            row = row < 0 ? 0 :
                  (row >= (long long)n_data ? n_data - 1 : row);
            unsigned p = atomicAdd(&g_meta[row].x, 1u);
            if (p < CAP) {
                g_list[(size_t)row * CAP + p] = (b << 24) | i;
            } else {   // Poisson-tail fallback, ~never
                const float* mr = memf + row * 128;
                const float* xr = x + b * 128;
                float s = 0.0f;
                for (int d = 0; d < 128; d++)
                    s += __ldg(mr + d) * __ldg(xr + d);
                logits[i] = s * T_INV;
            }
        }
    }

    // ===== software grid barrier (whole grid resident by construction) =====
    __syncthreads();
    if (tid == 0) {
        __threadfence();
        unsigned ticket = atomicAdd(&g_bar, 1u);
        unsigned target = (ticket / gridDim.x + 1u) * gridDim.x;
        while (*(volatile unsigned*)&g_bar < target) { }
        __threadfence();
    }
    __syncthreads();

    // ===== Phase B: sweep (R14 shape: 2 rows/warp, 16-lane halves) =====
    unsigned lane = tid & 31u;
    unsigned half = lane >> 4;
    unsigned hl = lane & 15u;
    unsigned hmask = 0xFFFFu << (half * 16u);
    unsigned warp = ((unsigned)blockIdx.x * blockDim.x + tid) >> 5;
    unsigned nwarps = ((unsigned)gridDim.x * blockDim.x) >> 5;

    const float4* xs0 = xs + hl;
    const float4* xs1 = xs + hl + 16u;

    for (unsigned rb = warp * 2u; rb < n_data; rb += nwarps * 2u) {
        unsigned r = rb + half;
        bool valid = r < n_data;
        unsigned rs = valid ? r : (n_data - 1u);

        float4 m0 = __ldcs(mem4 + rs * 32u + hl);
        float4 m1 = __ldcs(mem4 + rs * 32u + hl + 16u);
        uint2 meta = g_meta[rs];
        unsigned c = valid ? (meta.x > CAP ? CAP : meta.x) : 0u;
        unsigned upd = valid ? meta.y : 0u;

        unsigned co = __shfl_xor_sync(0xffffffffu, c, 16);
        unsigned cmax = c > co ? c : co;          // warp-uniform

        const uint4* lst4 = (const uint4*)(g_list + (size_t)rs * CAP);
        for (unsigned base = 0; base < cmax; base += 4u) {
            uint4 L = lst4[base >> 2];
            #pragma unroll
            for (int j = 0; j < 4; j++) {
                unsigned e = base + (unsigned)j;
                if (e >= cmax) break;             // warp-uniform exit
                bool act = e < c;
                unsigned ent = (j == 0) ? L.x : (j == 1) ? L.y
                             : (j == 2) ? L.z : L.w;
                unsigned b = (ent >> 24) & 15u;
                unsigned i = ent & 0xFFFFFFu;
                float4 xv0 = xs0[b * 32u];
                float4 xv1 = xs1[b * 32u];
                float s = m0.x * xv0.x + m0.y * xv0.y + m0.z * xv0.z +
                          m0.w * xv0.w + m1.x * xv1.x + m1.y * xv1.y +
                          m1.z * xv1.z + m1.w * xv1.w;
                #pragma unroll
                for (int off = 8; off; off >>= 1)
                    s += __shfl_xor_sync(0xffffffffu, s, off);
                if (act && hl == 0) logits[i] = s * T_INV;
            }
        }

        if (valid) {
            if (upd == 0) {
                float4* dst = out_mem4 + r * 32u;
                __stcs(dst + hl, m0);
                __stcs(dst + hl + 16u, m1);
            } else {
                unsigned b = upd - 1u;
                float4 xv0 = xs0[b * 32u];
                float4 xv1 = xs1[b * 32u];
                float4 v0, v1;
                v0.x = 0.5f * (m0.x + xv0.x); v0.y = 0.5f * (m0.y + xv0.y);
                v0.z = 0.5f * (m0.z + xv0.z); v0.w = 0.5f * (m0.w + xv0.w);
                v1.x = 0.5f * (m1.x + xv1.x); v1.y = 0.5f * (m1.y + xv1.y);
                v1.z = 0.5f * (m1.z + xv1.z); v1.w = 0.5f * (m1.w + xv1.w);
                float s = v0.x * v0.x + v0.y * v0.y + v0.z * v0.z +
                          v0.w * v0.w + v1.x * v1.x + v1.y * v1.y +
                          v1.z * v1.z + v1.w * v1.w;
                #pragma unroll
                for (int off = 8; off; off >>= 1)
                    s += __shfl_xor_sync(hmask, s, off);
                float inv = 1.0f / fmaxf(sqrtf(s), 1e-12f);
                v0.x *= inv; v0.y *= inv; v0.z *= inv; v0.w *= inv;
                v1.x *= inv; v1.y *= inv; v1.z *= inv; v1.w *= inv;
                float4* dst = out_mem4 + r * 32u;
                __stcs(dst + hl, v0);
                __stcs(dst + hl + 16u, v1);
            }
            // self-clean only if dirty (saves clean-row write traffic)
            if (hl == 0 && (meta.x | meta.y))
                g_meta[r] = make_uint2(0u, 0u);
        }
    }
}

// ---------------------------------------------------------------------------
// Fallback path (shape out of range): R2-proven kernels.
// ---------------------------------------------------------------------------
__global__ void copy_mem_kernel(const float4* __restrict__ src,
                                float4* __restrict__ dst, long long n4) {
    long long i = (long long)blockIdx.x * blockDim.x + threadIdx.x;
    long long stride = (long long)gridDim.x * blockDim.x;
    for (; i < n4; i += stride) dst[i] = src[i];
}

__global__ void logits_kernel(const float* __restrict__ x,
                              const void* __restrict__ y,
                              const void* __restrict__ idx,
                              const float* __restrict__ memory,
                              float* __restrict__ logits,
                              int bsz, unsigned Kp1, long long n_data) {
    __shared__ float4 xs[16 * 32];
    __shared__ int s_is64;
    int tid = threadIdx.x;
    if (tid == 0) s_is64 = sniff_is64(idx);
    int nx4 = bsz * 32;
    for (int i = tid; i < nx4; i += blockDim.x) xs[i] = ((const float4*)x)[i];
    __syncthreads();
    int is64 = s_is64;

    int lane = tid & 31;
    unsigned warp = (blockIdx.x * blockDim.x + tid) >> 5;
    unsigned nwarps = (gridDim.x * blockDim.x) >> 5;
    unsigned total = (unsigned)bsz * Kp1;

    for (unsigned i = warp; i < total; i += nwarps) {
        unsigned b = i / Kp1;
        unsigned k = i - b * Kp1;
        long long row = (k == 0) ? load_index(y, b, is64)
                                 : load_index(idx, i, is64);
        row = row < 0 ? 0 : (row >= n_data ? n_data - 1 : row);
        float4 mm = __ldg((const float4*)(memory + row * 128) + lane);
        float4 xv = xs[b * 32 + lane];
        float s = mm.x * xv.x + mm.y * xv.y + mm.z * xv.z + mm.w * xv.w;
        #pragma unroll
        for (int off = 16; off; off >>= 1)
            s += __shfl_xor_sync(0xffffffffu, s, off);
        if (lane == 0) logits[i] = s * T_INV;
    }
}

__global__ void update_kernel(const float* __restrict__ x,
                              const void* __restrict__ y,
                              const void* __restrict__ idx,
                              const float* __restrict__ memory,
                              float* __restrict__ out_mem,
                              float* __restrict__ out_labels,
                              int label_elems, long long n_data) {
    int b = blockIdx.x;
    int t = threadIdx.x;
    __shared__ int s_is64;
    if (t == 0) s_is64 = sniff_is64(idx);
    __syncthreads();
    long long row = load_index(y, (unsigned)b, s_is64);
    row = row < 0 ? 0 : (row >= n_data ? n_data - 1 : row);

    float v = memory[row * 128 + t] * 0.5f + x[b * 128 + t] * 0.5f;
    float s = v * v;
    #pragma unroll
    for (int off = 16; off; off >>= 1)
        s += __shfl_xor_sync(0xffffffffu, s, off);
    __shared__ float ws[4];
    if ((t & 31) == 0) ws[t >> 5] = s;
    __syncthreads();
    float tot = ws[0] + ws[1] + ws[2] + ws[3];
    float denom = fmaxf(sqrtf(tot), 1e-12f);
    out_mem[row * 128 + t] = v / denom;
    if (b == 0 && t < label_elems) out_labels[t] = 0.0f;
}

// ---------------------------------------------------------------------------
extern "C" void kernel_launch(void* const* d_in, const int* in_sizes, int n_in,
                              void* d_out, int out_size) {
    const float* x      = (const float*)d_in[0];   // [bsz, 128]
    const void*  y      = d_in[1];                 // [bsz]
    const void*  idx    = d_in[2];                 // [bsz, K+1]
    const float* memory = (const float*)d_in[3];   // [n_data, 128]

    int bsz = in_sizes[1];
    unsigned Kp1 = (unsigned)(in_sizes[2] / bsz);
    long long mem_elems = (long long)in_sizes[3];
    long long n_data = mem_elems / 128;
    long long logits_elems = (long long)bsz * Kp1;

    float* out = (float*)d_out;
    long long mem_off = (long long)out_size - mem_elems;
    if (mem_off < logits_elems) mem_off = logits_elems;
    float* out_mem = out + mem_off;
    float* out_labels = out + logits_elems;
    int label_elems = (int)(mem_off - logits_elems);

    int sms = 0;
    cudaDeviceGetAttribute(&sms, cudaDevAttrMultiProcessorCount, 0);
    if (sms <= 0) sms = 148;

    if (n_data <= MAX_ROWS && bsz <= 16 && logits_elems < (1 << 24)) {
        // single persistent kernel: grid == one resident wave (8 blk/SM)
        fused_kernel<<<sms * 8, 256>>>(x, y, idx, (const float4*)memory,
                                       (float4*)out_mem, out,
                                       out_labels, label_elems,
                                       bsz, Kp1, (unsigned)n_data);
    } else {
        copy_mem_kernel<<<2048, 256>>>((const float4*)memory,
                                       (float4*)out_mem, mem_elems / 4);
        logits_kernel<<<1184, 256>>>(x, y, idx, memory, out,
                                     bsz, Kp1, n_data);
        update_kernel<<<bsz, 128>>>(x, y, idx, memory, out_mem, out_labels,
                                    label_elems, n_data);
    }
}